// round 1
// baseline (speedup 1.0000x reference)
#include <cuda_runtime.h>
#include <math.h>

// Problem dims
#define BB   2
#define LL   2048
#define DM   1024
#define DI   2048
#define NS   16
#define RR   64
#define XD   96            // R + 2N
#define MR   (BB*LL)       // 4096 rows
#define EPSV 1e-5f

// ---------------- scratch (no alloc allowed) ----------------
__device__ __align__(128) float g_h   [(size_t)MR * DM];       // 16 MB
__device__ __align__(128) float g_xz  [(size_t)MR * 2 * DI];   // 64 MB
__device__ __align__(128) float g_u   [(size_t)MR * DI];       // 32 MB
__device__ __align__(128) float g_xd  [(size_t)MR * XD];       // 1.5 MB
__device__ __align__(128) float g_dt  [(size_t)MR * DI];       // 32 MB
__device__ __align__(128) float g_y   [(size_t)MR * DI];       // 32 MB

__device__ __forceinline__ float softplus_f(float v) {
    return v > 20.f ? v : log1pf(__expf(v));
}
__device__ __forceinline__ float silu_f(float v) {
    return v / (1.f + __expf(-v));
}

// ---------------- RMSNorm ----------------
__global__ void rmsnorm_k(const float* __restrict__ x,
                          const float* __restrict__ w,
                          float* __restrict__ out) {
    int row = blockIdx.x;
    const float4* xr = (const float4*)(x + (size_t)row * DM);
    float4 v = xr[threadIdx.x];                 // 256 threads * 4 = 1024
    float ss = v.x*v.x + v.y*v.y + v.z*v.z + v.w*v.w;
    #pragma unroll
    for (int m = 16; m; m >>= 1) ss += __shfl_xor_sync(~0u, ss, m);
    __shared__ float sred[8];
    __shared__ float stot;
    int wid = threadIdx.x >> 5;
    if ((threadIdx.x & 31) == 0) sred[wid] = ss;
    __syncthreads();
    if (threadIdx.x == 0) {
        float s = 0.f;
        #pragma unroll
        for (int i = 0; i < 8; i++) s += sred[i];
        stot = rsqrtf(s * (1.f / DM) + EPSV);
    }
    __syncthreads();
    float sc = stot;
    float4 wv = ((const float4*)w)[threadIdx.x];
    float4 o;
    o.x = v.x * sc * wv.x; o.y = v.y * sc * wv.y;
    o.z = v.z * sc * wv.z; o.w = v.w * sc * wv.w;
    ((float4*)(out + (size_t)row * DM))[threadIdx.x] = o;
}

// ---------------- SGEMM 128x128x8, 256 threads, 8x8 micro-tile ----------------
// C[M,N] = A[M,K](lda) @ B[K,N](ldb), epilogues:
//   EPI 0: plain  EPI 1: softplus(v + bias[col])  EPI 2: v + resid[row,col]
template<int EPI>
__global__ void __launch_bounds__(256, 2)
sgemm_k(const float* __restrict__ A, int lda,
        const float* __restrict__ B, int ldb,
        float* __restrict__ C, int ldc,
        int Ndim, int Kdim,
        const float* __restrict__ bias,
        const float* __restrict__ resid) {
    __shared__ float As[8][128];
    __shared__ float Bs[8][128];
    int tid = threadIdx.x;
    int tx4 = (tid & 15) * 4;
    int ty4 = (tid >> 4) * 4;
    int brow = blockIdx.y * 128;
    int bcol = blockIdx.x * 128;
    int arow = tid >> 1;
    int acol = (tid & 1) * 4;
    int bkr  = tid >> 5;
    int bcf  = (tid & 31) * 4;
    const float* Aptr = A + (size_t)(brow + arow) * lda + acol;
    const float* Bptr = B + (size_t)bkr * ldb + bcol + bcf;
    bool bguard = (bcol + bcf) < Ndim;

    float acc[8][8];
    #pragma unroll
    for (int i = 0; i < 8; i++)
        #pragma unroll
        for (int j = 0; j < 8; j++) acc[i][j] = 0.f;

    for (int kt = 0; kt < Kdim; kt += 8) {
        float4 av = *(const float4*)(Aptr + kt);
        float4 bv = make_float4(0.f, 0.f, 0.f, 0.f);
        if (bguard) bv = *(const float4*)(Bptr + (size_t)kt * ldb);
        __syncthreads();
        As[acol + 0][arow] = av.x;
        As[acol + 1][arow] = av.y;
        As[acol + 2][arow] = av.z;
        As[acol + 3][arow] = av.w;
        *(float4*)&Bs[bkr][bcf] = bv;
        __syncthreads();
        #pragma unroll
        for (int k = 0; k < 8; k++) {
            float4 a0 = *(const float4*)&As[k][ty4];
            float4 a1 = *(const float4*)&As[k][ty4 + 64];
            float4 b0 = *(const float4*)&Bs[k][tx4];
            float4 b1 = *(const float4*)&Bs[k][tx4 + 64];
            float ar[8] = {a0.x, a0.y, a0.z, a0.w, a1.x, a1.y, a1.z, a1.w};
            float br[8] = {b0.x, b0.y, b0.z, b0.w, b1.x, b1.y, b1.z, b1.w};
            #pragma unroll
            for (int i = 0; i < 8; i++)
                #pragma unroll
                for (int j = 0; j < 8; j++)
                    acc[i][j] = fmaf(ar[i], br[j], acc[i][j]);
        }
    }
    #pragma unroll
    for (int i = 0; i < 8; i++) {
        int r = brow + ty4 + (i & 3) + ((i >= 4) ? 64 : 0);
        #pragma unroll
        for (int g = 0; g < 2; g++) {
            int c = bcol + tx4 + g * 64;
            if (c < Ndim) {
                float v0 = acc[i][g*4+0], v1 = acc[i][g*4+1];
                float v2 = acc[i][g*4+2], v3 = acc[i][g*4+3];
                float4 o;
                if (EPI == 0) {
                    o = make_float4(v0, v1, v2, v3);
                } else if (EPI == 1) {
                    o.x = softplus_f(v0 + bias[c+0]);
                    o.y = softplus_f(v1 + bias[c+1]);
                    o.z = softplus_f(v2 + bias[c+2]);
                    o.w = softplus_f(v3 + bias[c+3]);
                } else {
                    const float4 rv = *(const float4*)(resid + (size_t)r * ldc + c);
                    o.x = v0 + rv.x; o.y = v1 + rv.y;
                    o.z = v2 + rv.z; o.w = v3 + rv.w;
                }
                *(float4*)(C + (size_t)r * ldc + c) = o;
            }
        }
    }
}

// ---------------- causal depthwise conv (K=4) + SiLU ----------------
__global__ void conv_silu_k(const float* __restrict__ xz,
                            const float* __restrict__ cw,
                            const float* __restrict__ cb,
                            float* __restrict__ u) {
    int d = blockIdx.x * 256 + threadIdx.x;  // 0..DI-1
    int l = blockIdx.y;
    int b = blockIdx.z;
    float4 w = ((const float4*)cw)[d];       // cw[d][0..3]
    size_t base = ((size_t)(b * LL) + l) * (2 * DI) + d;
    float acc = cb[d];
    const size_t stride = (size_t)2 * DI;
    if (l >= 3) acc = fmaf(xz[base - 3 * stride], w.x, acc);
    if (l >= 2) acc = fmaf(xz[base - 2 * stride], w.y, acc);
    if (l >= 1) acc = fmaf(xz[base - 1 * stride], w.z, acc);
    acc = fmaf(xz[base], w.w, acc);
    u[((size_t)(b * LL) + l) * DI + d] = silu_f(acc);
}

// ---------------- selective scan ----------------
// 16 chains per block (d = d0..d0+15, same b). lane n of each 16-lane group
// owns state n. B/C rows (shared by ALL d-chains at a given (b,t)) are staged
// in SMEM per 64-step chunk.
__global__ void __launch_bounds__(256) scan_k(
    const float* __restrict__ xdbl, const float* __restrict__ dt,
    const float* __restrict__ u,    const float* __restrict__ Alog,
    const float* __restrict__ Dp,   float* __restrict__ y) {
    __shared__ float sBC[64][32];
    int tid = threadIdx.x;
    int g = tid >> 4, n = tid & 15;
    int b = blockIdx.x >> 7;                  // DI/16 = 128 blocks per batch
    int d = ((blockIdx.x & 127) << 4) + g;
    float An = -expf(Alog[d * NS + n]);
    float Dd = Dp[d];
    float h = 0.f;
    size_t rowbase = (size_t)b * LL;
    for (int c = 0; c < LL / 64; c++) {
        __syncthreads();
        for (int i = tid; i < 64 * 32; i += 256) {
            int tt = i >> 5, col = i & 31;
            sBC[tt][col] = xdbl[(rowbase + c * 64 + tt) * XD + 64 + col];
        }
        __syncthreads();
        for (int tt = 0; tt < 64; tt++) {
            size_t idx = (rowbase + c * 64 + tt) * DI + d;
            float dtv = __ldg(dt + idx);      // broadcast within group
            float uv  = __ldg(u + idx);
            float Bv = sBC[tt][n];
            float Cv = sBC[tt][16 + n];
            float dA = __expf(dtv * An);
            h = fmaf(dA, h, dtv * Bv * uv);
            float p = h * Cv;
            p += __shfl_xor_sync(0xffffffffu, p, 8, 16);
            p += __shfl_xor_sync(0xffffffffu, p, 4, 16);
            p += __shfl_xor_sync(0xffffffffu, p, 2, 16);
            p += __shfl_xor_sync(0xffffffffu, p, 1, 16);
            if (n == 0) y[idx] = p + uv * Dd;
        }
    }
}

// ---------------- gate: y *= silu(z) ----------------
__global__ void gate_k(const float* __restrict__ xz, float* __restrict__ y) {
    size_t i = (size_t)blockIdx.x * blockDim.x + threadIdx.x;  // over MR*DI/4
    size_t m = i >> 9;         // /(DI/4=512)
    size_t c = i & 511;
    float4 z = ((const float4*)xz)[m * 1024 + 512 + c];        // z half of xz row
    float4 yv = ((float4*)y)[i];
    yv.x *= silu_f(z.x);
    yv.y *= silu_f(z.y);
    yv.z *= silu_f(z.z);
    yv.w *= silu_f(z.w);
    ((float4*)y)[i] = yv;
}

// ---------------- launcher ----------------
extern "C" void kernel_launch(void* const* d_in, const int* in_sizes, int n_in,
                              void* d_out, int out_size) {
    const float* x         = (const float*)d_in[0];
    // d_in[1] = hormone_vectors (unused by reference)
    const float* norm_w    = (const float*)d_in[2];
    const float* in_proj_w = (const float*)d_in[3];
    const float* conv_w    = (const float*)d_in[4];
    const float* conv_b    = (const float*)d_in[5];
    const float* x_proj_w  = (const float*)d_in[6];
    const float* dt_proj_w = (const float*)d_in[7];
    const float* dt_proj_b = (const float*)d_in[8];
    const float* A_log     = (const float*)d_in[9];
    const float* Dp        = (const float*)d_in[10];
    const float* out_proj_w= (const float*)d_in[11];
    float* out = (float*)d_out;

    float *h, *xz, *u, *xd, *dt, *y;
    cudaGetSymbolAddress((void**)&h,  g_h);
    cudaGetSymbolAddress((void**)&xz, g_xz);
    cudaGetSymbolAddress((void**)&u,  g_u);
    cudaGetSymbolAddress((void**)&xd, g_xd);
    cudaGetSymbolAddress((void**)&dt, g_dt);
    cudaGetSymbolAddress((void**)&y,  g_y);

    // 1. h = rmsnorm(x)
    rmsnorm_k<<<MR, 256>>>(x, norm_w, h);
    // 2. xz = h @ in_proj_w   (4096x1024 @ 1024x4096)
    sgemm_k<0><<<dim3(32, 32), 256>>>(h, DM, in_proj_w, 2 * DI, xz, 2 * DI,
                                      2 * DI, DM, nullptr, nullptr);
    // 3. u = silu(causal_conv(xz[..., :DI]))
    conv_silu_k<<<dim3(DI / 256, LL, BB), 256>>>(xz, conv_w, conv_b, u);
    // 4. xdbl = u @ x_proj_w  (4096x2048 @ 2048x96)
    sgemm_k<0><<<dim3(1, 32), 256>>>(u, DI, x_proj_w, XD, xd, XD,
                                     XD, DI, nullptr, nullptr);
    // 5. dt = softplus(xdbl[:, :64] @ dt_proj_w + dt_proj_b)  (4096x64 @ 64x2048)
    sgemm_k<1><<<dim3(16, 32), 256>>>(xd, XD, dt_proj_w, DI, dt, DI,
                                      DI, RR, dt_proj_b, nullptr);
    // 6. selective scan -> y (includes + u*D)
    scan_k<<<BB * DI / 16, 256>>>(xd, dt, u, A_log, Dp, y);
    // 7. y *= silu(z)
    gate_k<<<(MR * DI / 4) / 256, 256>>>(xz, y);
    // 8. out = x + y @ out_proj_w  (4096x2048 @ 2048x1024)
    sgemm_k<2><<<dim3(8, 32), 256>>>(y, DI, out_proj_w, DM, out, DM,
                                     DM, DI, nullptr, x);
}

// round 3
// speedup vs baseline: 1.5521x; 1.5521x over previous
#include <cuda_runtime.h>
#include <cuda_bf16.h>
#include <math.h>
#include <stdint.h>

// Problem dims
#define BB   2
#define LL   2048
#define DM   1024
#define DI   2048
#define NS   16
#define RR   64
#define XD   96            // R + 2N
#define MR   (BB*LL)       // 4096 rows
#define EPSV 1e-5f

// ---------------- scratch (no alloc allowed) ----------------
__device__ __align__(128) float g_xz  [(size_t)MR * 2 * DI];
__device__ __align__(128) float g_xd  [(size_t)MR * XD];
__device__ __align__(128) float g_dt  [(size_t)MR * DI];
__device__ __align__(128) float g_y   [(size_t)MR * DI];

__device__ __align__(128) __nv_bfloat16 g_h_hi [(size_t)MR * DM];
__device__ __align__(128) __nv_bfloat16 g_h_lo [(size_t)MR * DM];
__device__ __align__(128) __nv_bfloat16 g_u_hi [(size_t)MR * DI];
__device__ __align__(128) __nv_bfloat16 g_u_lo [(size_t)MR * DI];
__device__ __align__(128) __nv_bfloat16 g_xd_hi[(size_t)MR * XD];
__device__ __align__(128) __nv_bfloat16 g_xd_lo[(size_t)MR * XD];
__device__ __align__(128) __nv_bfloat16 g_yg_hi[(size_t)MR * DI];
__device__ __align__(128) __nv_bfloat16 g_yg_lo[(size_t)MR * DI];
// transposed weights [N,K] bf16 hi/lo
__device__ __align__(128) __nv_bfloat16 g_wi_hi[(size_t)(2*DI) * DM];
__device__ __align__(128) __nv_bfloat16 g_wi_lo[(size_t)(2*DI) * DM];
__device__ __align__(128) __nv_bfloat16 g_wx_hi[(size_t)XD * DI];
__device__ __align__(128) __nv_bfloat16 g_wx_lo[(size_t)XD * DI];
__device__ __align__(128) __nv_bfloat16 g_wd_hi[(size_t)DI * RR];
__device__ __align__(128) __nv_bfloat16 g_wd_lo[(size_t)DI * RR];
__device__ __align__(128) __nv_bfloat16 g_wo_hi[(size_t)DM * DI];
__device__ __align__(128) __nv_bfloat16 g_wo_lo[(size_t)DM * DI];

// ================= baseline-PTX helpers (no sm_103a-only ops) =============
__device__ __forceinline__ uint32_t smem_to_u32(const void* p) {
    uint32_t a;
    asm("{ .reg .u64 t; cvta.to.shared.u64 t, %1; cvt.u32.u64 %0, t; }" : "=r"(a) : "l"(p));
    return a;
}
#define CP_ASYNC16(dst, src) \
    asm volatile("cp.async.cg.shared.global [%0], [%1], 16;" :: "r"(dst), "l"(src))
#define CP_ASYNC16_P(dst, src, p) \
    asm volatile("{\n\t.reg .pred q;\n\t.reg .b32 sz;\n\t" \
                 "setp.ne.u32 q, %2, 0;\n\tselp.b32 sz, 16, 0, q;\n\t" \
                 "cp.async.cg.shared.global [%0], [%1], 16, sz;\n\t}" \
                 :: "r"(dst), "l"(src), "r"(p))
#define CP_COMMIT() asm volatile("cp.async.commit_group;" ::: "memory")
#define CP_WAIT(N)  asm volatile("cp.async.wait_group %0;" :: "n"(N) : "memory")
#define LDMX4(r0, r1, r2, r3, addr) \
    asm volatile("ldmatrix.sync.aligned.m8n8.x4.shared.b16 {%0,%1,%2,%3}, [%4];" \
                 : "=r"(r0), "=r"(r1), "=r"(r2), "=r"(r3) : "r"(addr))
#define MMA16816(d, a, b) \
    asm volatile("mma.sync.aligned.m16n8k16.row.col.f32.bf16.bf16.f32 " \
                 "{%0,%1,%2,%3}, {%4,%5,%6,%7}, {%8,%9}, {%0,%1,%2,%3};" \
                 : "+f"((d)[0]), "+f"((d)[1]), "+f"((d)[2]), "+f"((d)[3]) \
                 : "r"((a)[0]), "r"((a)[1]), "r"((a)[2]), "r"((a)[3]), \
                   "r"((b)[0]), "r"((b)[1]))

// ---------------- math helpers ----------------
__device__ __forceinline__ float softplus_f(float v) {
    return v > 20.f ? v : log1pf(__expf(v));
}
__device__ __forceinline__ float silu_f(float v) {
    return v / (1.f + __expf(-v));
}
__device__ __forceinline__ void split_bf16(float v, __nv_bfloat16& hi, __nv_bfloat16& lo) {
    hi = __float2bfloat16(v);
    lo = __float2bfloat16(v - __bfloat162float(hi));
}

// ================= RMSNorm -> bf16 hi/lo =================
__global__ void rmsnorm_k(const float* __restrict__ x,
                          const float* __restrict__ w,
                          __nv_bfloat16* __restrict__ ohi,
                          __nv_bfloat16* __restrict__ olo) {
    int row = blockIdx.x;
    const float4* xr = (const float4*)(x + (size_t)row * DM);
    float4 v = xr[threadIdx.x];
    float ss = v.x*v.x + v.y*v.y + v.z*v.z + v.w*v.w;
    #pragma unroll
    for (int m = 16; m; m >>= 1) ss += __shfl_xor_sync(~0u, ss, m);
    __shared__ float sred[8];
    __shared__ float stot;
    int wid = threadIdx.x >> 5;
    if ((threadIdx.x & 31) == 0) sred[wid] = ss;
    __syncthreads();
    if (threadIdx.x == 0) {
        float s = 0.f;
        #pragma unroll
        for (int i = 0; i < 8; i++) s += sred[i];
        stot = rsqrtf(s * (1.f / DM) + EPSV);
    }
    __syncthreads();
    float sc = stot;
    float4 wv = ((const float4*)w)[threadIdx.x];
    float o[4] = {v.x*sc*wv.x, v.y*sc*wv.y, v.z*sc*wv.z, v.w*sc*wv.w};
    size_t base = (size_t)row * DM + threadIdx.x * 4;
    #pragma unroll
    for (int j = 0; j < 4; j++) {
        __nv_bfloat16 hi, lo; split_bf16(o[j], hi, lo);
        ohi[base + j] = hi; olo[base + j] = lo;
    }
}

// ================= transpose + bf16 hi/lo split =================
__global__ void transcvt_k(const float* __restrict__ in, int R, int C,
                           __nv_bfloat16* __restrict__ ohi,
                           __nv_bfloat16* __restrict__ olo) {
    __shared__ float t[32][33];
    int ct = blockIdx.x * 32, rt = blockIdx.y * 32;
    int tx = threadIdx.x & 31, ty4 = (threadIdx.x >> 5) * 4;
    #pragma unroll
    for (int j = 0; j < 4; j++) {
        int r = rt + ty4 + j;
        t[ty4 + j][tx] = in[(size_t)r * C + ct + tx];
    }
    __syncthreads();
    #pragma unroll
    for (int j = 0; j < 4; j++) {
        int c = ct + ty4 + j;
        float v = t[tx][ty4 + j];
        __nv_bfloat16 hi, lo; split_bf16(v, hi, lo);
        size_t o = (size_t)c * R + rt + tx;
        ohi[o] = hi; olo[o] = lo;
    }
}

// ================= HMMA bf16x3 GEMM =================
// C[M,N] = A[M,K] @ Bt^T, Bt[N,K]. 128x128 CTA tile, BK=32, 8 warps (4x2),
// warp tile 32x64. fp32-ish accuracy via (Ahi*Bhi + Ahi*Blo + Alo*Bhi).
// EPI 0: plain   1: softplus(v+bias[col])   2: v+resid[row,col]
// EPI 3: fp32 store + bf16 hi/lo split stores
#define SMS    80                    // smem row stride bytes (40 halves)
#define T_A_LO 10240
#define T_B_HI 20480
#define T_B_LO 30720
#define T_STG  40960
#define SMEMB  (2 * T_STG)

template<int EPI>
__global__ void __launch_bounds__(256, 1)
mma_gemm_k(const __nv_bfloat16* __restrict__ Ahi, const __nv_bfloat16* __restrict__ Alo, int lda,
           const __nv_bfloat16* __restrict__ Bhi, const __nv_bfloat16* __restrict__ Blo,
           float* __restrict__ C, int ldc, int Kdim, int Ndim,
           const float* __restrict__ bias, const float* __restrict__ resid,
           __nv_bfloat16* __restrict__ Chi, __nv_bfloat16* __restrict__ Clo) {
    extern __shared__ char smem[];
    const uint32_t sdata = smem_to_u32(smem);
    const int tid = threadIdx.x;
    const int wid = tid >> 5, lane = tid & 31;
    const int wm = wid & 3, wn = wid >> 2;          // 4 x 2 warp grid
    const int brow = blockIdx.y * 128;
    const int bcol = blockIdx.x * 128;
    const int NC = Kdim >> 5;                       // 32-wide K chunks

    // per-thread load coords: 512 16B segments per matrix, 2 iters x 256 thr
    const int lrow = tid >> 2;                      // +128 on second iter? no: idx>>2
    const int lseg = tid & 3;

    float acc[2][8][4];
    #pragma unroll
    for (int a = 0; a < 2; a++)
        #pragma unroll
        for (int b = 0; b < 8; b++)
            #pragma unroll
            for (int c = 0; c < 4; c++) acc[a][b][c] = 0.f;

    // ---- async stage loader ----
    auto issue = [&](int i) {
        uint32_t stb = sdata + (i & 1) * T_STG;
        int koff = i * 32;
        #pragma unroll
        for (int it = 0; it < 2; it++) {
            int row = it * 64 + lrow;
            uint32_t so = stb + row * SMS + lseg * 16;
            size_t gao = (size_t)(brow + row) * lda + koff + lseg * 8;
            CP_ASYNC16(so,          Ahi + gao);
            CP_ASYNC16(so + T_A_LO, Alo + gao);
            int bn = bcol + row;
            uint32_t p = (bn < Ndim) ? 1u : 0u;
            size_t gbo = (size_t)bn * Kdim + koff + lseg * 8;
            CP_ASYNC16_P(so + T_B_HI, Bhi + gbo, p);
            CP_ASYNC16_P(so + T_B_LO, Blo + gbo, p);
        }
        CP_COMMIT();
    };

    issue(0);
    for (int i = 0; i < NC; i++) {
        if (i + 1 < NC) { issue(i + 1); CP_WAIT(1); }
        else           { CP_WAIT(0); }
        __syncthreads();
        uint32_t stb = sdata + (i & 1) * T_STG;
        // fragment row/col pieces for ldmatrix
        const int fr = lane & 15;                   // row within 16
        const int fc = (lane >> 4) * 8;             // k offset 0/8
        #pragma unroll
        for (int ks = 0; ks < 32; ks += 16) {
            uint32_t ah[2][4], al[2][4], bh[8][2], bl[8][2];
            #pragma unroll
            for (int mt = 0; mt < 2; mt++) {
                uint32_t ad = stb + (wm * 32 + mt * 16 + fr) * SMS + (ks + fc) * 2;
                LDMX4(ah[mt][0], ah[mt][1], ah[mt][2], ah[mt][3], ad);
                LDMX4(al[mt][0], al[mt][1], al[mt][2], al[mt][3], ad + T_A_LO);
            }
            #pragma unroll
            for (int bt = 0; bt < 4; bt++) {
                uint32_t bd = stb + T_B_HI + (wn * 64 + bt * 16 + fr) * SMS + (ks + fc) * 2;
                uint32_t r0, r1, r2, r3;
                LDMX4(r0, r1, r2, r3, bd);
                bh[bt*2][0] = r0; bh[bt*2][1] = r2;
                bh[bt*2+1][0] = r1; bh[bt*2+1][1] = r3;
                LDMX4(r0, r1, r2, r3, bd + (T_B_LO - T_B_HI));
                bl[bt*2][0] = r0; bl[bt*2][1] = r2;
                bl[bt*2+1][0] = r1; bl[bt*2+1][1] = r3;
            }
            #pragma unroll
            for (int mt = 0; mt < 2; mt++)
                #pragma unroll
                for (int nt = 0; nt < 8; nt++) {
                    MMA16816(acc[mt][nt], ah[mt], bh[nt]);
                    MMA16816(acc[mt][nt], ah[mt], bl[nt]);
                    MMA16816(acc[mt][nt], al[mt], bh[nt]);
                }
        }
        __syncthreads();
    }

    // ---- epilogue ----
    const int lr = lane >> 2;
    const int lc = (lane & 3) * 2;
    #pragma unroll
    for (int mt = 0; mt < 2; mt++) {
        int r0 = brow + wm * 32 + mt * 16 + lr;
        #pragma unroll
        for (int nt = 0; nt < 8; nt++) {
            int c = bcol + wn * 64 + nt * 8 + lc;
            if (c >= Ndim) continue;
            #pragma unroll
            for (int hh = 0; hh < 2; hh++) {
                int r = r0 + hh * 8;
                float v0 = acc[mt][nt][hh*2], v1 = acc[mt][nt][hh*2+1];
                if (EPI == 1) {
                    v0 = softplus_f(v0 + bias[c]);
                    v1 = softplus_f(v1 + bias[c+1]);
                } else if (EPI == 2) {
                    const float* rr = resid + (size_t)r * ldc + c;
                    v0 += rr[0]; v1 += rr[1];
                }
                float* cp = C + (size_t)r * ldc + c;
                *(float2*)cp = make_float2(v0, v1);
                if (EPI == 3) {
                    size_t hb = (size_t)r * ldc + c;
                    __nv_bfloat16 h0, l0, h1, l1;
                    split_bf16(v0, h0, l0); split_bf16(v1, h1, l1);
                    Chi[hb] = h0; Chi[hb+1] = h1;
                    Clo[hb] = l0; Clo[hb+1] = l1;
                }
            }
        }
    }
}

// ================= causal depthwise conv (K=4) + SiLU -> bf16 hi/lo ========
__global__ void conv_silu_k(const float* __restrict__ xz,
                            const float* __restrict__ cw,
                            const float* __restrict__ cb,
                            __nv_bfloat16* __restrict__ uhi,
                            __nv_bfloat16* __restrict__ ulo) {
    int d = blockIdx.x * 256 + threadIdx.x;
    int l = blockIdx.y;
    int b = blockIdx.z;
    float4 w = ((const float4*)cw)[d];
    size_t base = ((size_t)(b * LL) + l) * (2 * DI) + d;
    float acc = cb[d];
    const size_t stride = (size_t)2 * DI;
    if (l >= 3) acc = fmaf(xz[base - 3 * stride], w.x, acc);
    if (l >= 2) acc = fmaf(xz[base - 2 * stride], w.y, acc);
    if (l >= 1) acc = fmaf(xz[base - 1 * stride], w.z, acc);
    acc = fmaf(xz[base], w.w, acc);
    float u = silu_f(acc);
    __nv_bfloat16 hi, lo; split_bf16(u, hi, lo);
    size_t o = ((size_t)(b * LL) + l) * DI + d;
    uhi[o] = hi; ulo[o] = lo;
}

// ================= selective scan =================
__global__ void __launch_bounds__(256) scan_k(
    const float* __restrict__ xdbl, const float* __restrict__ dt,
    const __nv_bfloat16* __restrict__ uhi, const __nv_bfloat16* __restrict__ ulo,
    const float* __restrict__ Alog, const float* __restrict__ Dp,
    float* __restrict__ y) {
    __shared__ float sBC[64][32];
    int tid = threadIdx.x;
    int g = tid >> 4, n = tid & 15;
    int b = blockIdx.x >> 7;
    int d = ((blockIdx.x & 127) << 4) + g;
    float An = -expf(Alog[d * NS + n]);
    float Dd = Dp[d];
    float h = 0.f;
    size_t rowbase = (size_t)b * LL;
    for (int c = 0; c < LL / 64; c++) {
        __syncthreads();
        for (int i = tid; i < 64 * 32; i += 256) {
            int tt = i >> 5, col = i & 31;
            sBC[tt][col] = xdbl[(rowbase + c * 64 + tt) * XD + 64 + col];
        }
        __syncthreads();
        for (int tt = 0; tt < 64; tt++) {
            size_t idx = (rowbase + c * 64 + tt) * DI + d;
            float dtv = __ldg(dt + idx);
            float uv  = __bfloat162float(uhi[idx]) + __bfloat162float(ulo[idx]);
            float Bv = sBC[tt][n];
            float Cv = sBC[tt][16 + n];
            float dA = __expf(dtv * An);
            h = fmaf(dA, h, dtv * Bv * uv);
            float p = h * Cv;
            p += __shfl_xor_sync(0xffffffffu, p, 8, 16);
            p += __shfl_xor_sync(0xffffffffu, p, 4, 16);
            p += __shfl_xor_sync(0xffffffffu, p, 2, 16);
            p += __shfl_xor_sync(0xffffffffu, p, 1, 16);
            if (n == 0) y[idx] = p + uv * Dd;
        }
    }
}

// ================= gate: yg = y * silu(z) -> bf16 hi/lo =================
__global__ void gate_k(const float* __restrict__ xz, const float* __restrict__ y,
                       __nv_bfloat16* __restrict__ ghi, __nv_bfloat16* __restrict__ glo) {
    size_t i = (size_t)blockIdx.x * blockDim.x + threadIdx.x;
    size_t m = i >> 9;
    size_t c = i & 511;
    float4 z  = ((const float4*)xz)[m * 1024 + 512 + c];
    float4 yv = ((const float4*)y)[i];
    float o[4] = {yv.x * silu_f(z.x), yv.y * silu_f(z.y),
                  yv.z * silu_f(z.z), yv.w * silu_f(z.w)};
    size_t base = i * 4;
    #pragma unroll
    for (int j = 0; j < 4; j++) {
        __nv_bfloat16 hi, lo; split_bf16(o[j], hi, lo);
        ghi[base + j] = hi; glo[base + j] = lo;
    }
}

// ================= launcher =================
extern "C" void kernel_launch(void* const* d_in, const int* in_sizes, int n_in,
                              void* d_out, int out_size) {
    const float* x         = (const float*)d_in[0];
    const float* norm_w    = (const float*)d_in[2];
    const float* in_proj_w = (const float*)d_in[3];
    const float* conv_w    = (const float*)d_in[4];
    const float* conv_b    = (const float*)d_in[5];
    const float* x_proj_w  = (const float*)d_in[6];
    const float* dt_proj_w = (const float*)d_in[7];
    const float* dt_proj_b = (const float*)d_in[8];
    const float* A_log     = (const float*)d_in[9];
    const float* Dp        = (const float*)d_in[10];
    const float* out_proj_w= (const float*)d_in[11];
    float* out = (float*)d_out;

    float *xz, *xd, *dt, *y;
    cudaGetSymbolAddress((void**)&xz, g_xz);
    cudaGetSymbolAddress((void**)&xd, g_xd);
    cudaGetSymbolAddress((void**)&dt, g_dt);
    cudaGetSymbolAddress((void**)&y,  g_y);
    __nv_bfloat16 *h_hi, *h_lo, *u_hi, *u_lo, *xd_hi, *xd_lo, *yg_hi, *yg_lo;
    __nv_bfloat16 *wi_hi, *wi_lo, *wx_hi, *wx_lo, *wd_hi, *wd_lo, *wo_hi, *wo_lo;
    cudaGetSymbolAddress((void**)&h_hi,  g_h_hi);  cudaGetSymbolAddress((void**)&h_lo,  g_h_lo);
    cudaGetSymbolAddress((void**)&u_hi,  g_u_hi);  cudaGetSymbolAddress((void**)&u_lo,  g_u_lo);
    cudaGetSymbolAddress((void**)&xd_hi, g_xd_hi); cudaGetSymbolAddress((void**)&xd_lo, g_xd_lo);
    cudaGetSymbolAddress((void**)&yg_hi, g_yg_hi); cudaGetSymbolAddress((void**)&yg_lo, g_yg_lo);
    cudaGetSymbolAddress((void**)&wi_hi, g_wi_hi); cudaGetSymbolAddress((void**)&wi_lo, g_wi_lo);
    cudaGetSymbolAddress((void**)&wx_hi, g_wx_hi); cudaGetSymbolAddress((void**)&wx_lo, g_wx_lo);
    cudaGetSymbolAddress((void**)&wd_hi, g_wd_hi); cudaGetSymbolAddress((void**)&wd_lo, g_wd_lo);
    cudaGetSymbolAddress((void**)&wo_hi, g_wo_hi); cudaGetSymbolAddress((void**)&wo_lo, g_wo_lo);

    cudaFuncSetAttribute(mma_gemm_k<0>, cudaFuncAttributeMaxDynamicSharedMemorySize, SMEMB);
    cudaFuncSetAttribute(mma_gemm_k<1>, cudaFuncAttributeMaxDynamicSharedMemorySize, SMEMB);
    cudaFuncSetAttribute(mma_gemm_k<2>, cudaFuncAttributeMaxDynamicSharedMemorySize, SMEMB);
    cudaFuncSetAttribute(mma_gemm_k<3>, cudaFuncAttributeMaxDynamicSharedMemorySize, SMEMB);

    // 0. weight transpose + bf16 split
    transcvt_k<<<dim3((2*DI)/32, DM/32), 256>>>(in_proj_w, DM, 2*DI, wi_hi, wi_lo);
    transcvt_k<<<dim3(XD/32, DI/32), 256>>>(x_proj_w, DI, XD, wx_hi, wx_lo);
    transcvt_k<<<dim3(DI/32, RR/32), 256>>>(dt_proj_w, RR, DI, wd_hi, wd_lo);
    transcvt_k<<<dim3(DM/32, DI/32), 256>>>(out_proj_w, DI, DM, wo_hi, wo_lo);
    // 1. h = rmsnorm(x) -> bf16 hi/lo
    rmsnorm_k<<<MR, 256>>>(x, norm_w, h_hi, h_lo);
    // 2. xz = h @ in_proj_w  (4096x1024 @ 1024x4096)
    mma_gemm_k<0><<<dim3((2*DI)/128, MR/128), 256, SMEMB>>>(
        h_hi, h_lo, DM, wi_hi, wi_lo, xz, 2*DI, DM, 2*DI,
        nullptr, nullptr, nullptr, nullptr);
    // 3. u = silu(causal_conv(xz[..., :DI])) -> bf16 hi/lo
    conv_silu_k<<<dim3(DI/256, LL, BB), 256>>>(xz, conv_w, conv_b, u_hi, u_lo);
    // 4. xdbl = u @ x_proj_w  (4096x2048 @ 2048x96) -> fp32 + hi/lo
    mma_gemm_k<3><<<dim3(1, MR/128), 256, SMEMB>>>(
        u_hi, u_lo, DI, wx_hi, wx_lo, xd, XD, DI, XD,
        nullptr, nullptr, xd_hi, xd_lo);
    // 5. dt = softplus(xdbl[:, :64] @ dt_proj_w + b)  (4096x64 @ 64x2048)
    mma_gemm_k<1><<<dim3(DI/128, MR/128), 256, SMEMB>>>(
        xd_hi, xd_lo, XD, wd_hi, wd_lo, dt, DI, RR, DI,
        dt_proj_b, nullptr, nullptr, nullptr);
    // 6. selective scan -> y fp32 (includes + u*D)
    scan_k<<<BB * DI / 16, 256>>>(xd, dt, u_hi, u_lo, A_log, Dp, y);
    // 7. yg = y * silu(z) -> bf16 hi/lo
    gate_k<<<(MR * DI / 4) / 256, 256>>>(xz, y, yg_hi, yg_lo);
    // 8. out = x + yg @ out_proj_w  (4096x2048 @ 2048x1024)
    mma_gemm_k<2><<<dim3(DM/128, MR/128), 256, SMEMB>>>(
        yg_hi, yg_lo, DI, wo_hi, wo_lo, out, DM, DI, DM,
        nullptr, x, nullptr, nullptr);
}

// round 4
// speedup vs baseline: 1.6452x; 1.0600x over previous
#include <cuda_runtime.h>
#include <cuda_bf16.h>
#include <math.h>
#include <stdint.h>

// Problem dims
#define BB   2
#define LL   2048
#define DM   1024
#define DI   2048
#define NS   16
#define RR   64
#define XD   96            // R + 2N
#define MR   (BB*LL)       // 4096 rows
#define EPSV 1e-5f
#define XKS  8             // split-K factor for x_proj

// ---------------- scratch (no alloc allowed) ----------------
__device__ __align__(128) float g_xz  [(size_t)MR * 2 * DI];
__device__ __align__(128) float g_xd  [(size_t)MR * XD];
__device__ __align__(128) float g_xdp [(size_t)XKS * MR * XD];  // split-K partials
__device__ __align__(128) float g_dt  [(size_t)MR * DI];
__device__ __align__(128) float g_y   [(size_t)MR * DI];

__device__ __align__(128) __nv_bfloat16 g_h_hi [(size_t)MR * DM];
__device__ __align__(128) __nv_bfloat16 g_h_lo [(size_t)MR * DM];
__device__ __align__(128) __nv_bfloat16 g_u_hi [(size_t)MR * DI];
__device__ __align__(128) __nv_bfloat16 g_u_lo [(size_t)MR * DI];
__device__ __align__(128) __nv_bfloat16 g_xd_hi[(size_t)MR * XD];
__device__ __align__(128) __nv_bfloat16 g_xd_lo[(size_t)MR * XD];
__device__ __align__(128) __nv_bfloat16 g_yg_hi[(size_t)MR * DI];
__device__ __align__(128) __nv_bfloat16 g_yg_lo[(size_t)MR * DI];
// transposed weights [N,K] bf16 hi/lo
__device__ __align__(128) __nv_bfloat16 g_wi_hi[(size_t)(2*DI) * DM];
__device__ __align__(128) __nv_bfloat16 g_wi_lo[(size_t)(2*DI) * DM];
__device__ __align__(128) __nv_bfloat16 g_wx_hi[(size_t)XD * DI];
__device__ __align__(128) __nv_bfloat16 g_wx_lo[(size_t)XD * DI];
__device__ __align__(128) __nv_bfloat16 g_wd_hi[(size_t)DI * RR];
__device__ __align__(128) __nv_bfloat16 g_wd_lo[(size_t)DI * RR];
__device__ __align__(128) __nv_bfloat16 g_wo_hi[(size_t)DM * DI];
__device__ __align__(128) __nv_bfloat16 g_wo_lo[(size_t)DM * DI];

// ================= baseline-PTX helpers (no sm_103a-only ops) =============
__device__ __forceinline__ uint32_t smem_to_u32(const void* p) {
    uint32_t a;
    asm("{ .reg .u64 t; cvta.to.shared.u64 t, %1; cvt.u32.u64 %0, t; }" : "=r"(a) : "l"(p));
    return a;
}
#define CP_ASYNC16(dst, src) \
    asm volatile("cp.async.cg.shared.global [%0], [%1], 16;" :: "r"(dst), "l"(src))
#define CP_ASYNC16_P(dst, src, p) \
    asm volatile("{\n\t.reg .pred q;\n\t.reg .b32 sz;\n\t" \
                 "setp.ne.u32 q, %2, 0;\n\tselp.b32 sz, 16, 0, q;\n\t" \
                 "cp.async.cg.shared.global [%0], [%1], 16, sz;\n\t}" \
                 :: "r"(dst), "l"(src), "r"(p))
#define CP_COMMIT() asm volatile("cp.async.commit_group;" ::: "memory")
#define CP_WAIT(N)  asm volatile("cp.async.wait_group %0;" :: "n"(N) : "memory")
#define LDMX4(r0, r1, r2, r3, addr) \
    asm volatile("ldmatrix.sync.aligned.m8n8.x4.shared.b16 {%0,%1,%2,%3}, [%4];" \
                 : "=r"(r0), "=r"(r1), "=r"(r2), "=r"(r3) : "r"(addr))
#define MMA16816(d, a, b) \
    asm volatile("mma.sync.aligned.m16n8k16.row.col.f32.bf16.bf16.f32 " \
                 "{%0,%1,%2,%3}, {%4,%5,%6,%7}, {%8,%9}, {%0,%1,%2,%3};" \
                 : "+f"((d)[0]), "+f"((d)[1]), "+f"((d)[2]), "+f"((d)[3]) \
                 : "r"((a)[0]), "r"((a)[1]), "r"((a)[2]), "r"((a)[3]), \
                   "r"((b)[0]), "r"((b)[1]))

// ---------------- math helpers ----------------
__device__ __forceinline__ float softplus_f(float v) {
    return v > 20.f ? v : log1pf(__expf(v));
}
__device__ __forceinline__ float silu_f(float v) {
    return v / (1.f + __expf(-v));
}
__device__ __forceinline__ void split_bf16(float v, __nv_bfloat16& hi, __nv_bfloat16& lo) {
    hi = __float2bfloat16(v);
    lo = __float2bfloat16(v - __bfloat162float(hi));
}

// ================= RMSNorm -> bf16 hi/lo =================
__global__ void rmsnorm_k(const float* __restrict__ x,
                          const float* __restrict__ w,
                          __nv_bfloat16* __restrict__ ohi,
                          __nv_bfloat16* __restrict__ olo) {
    int row = blockIdx.x;
    const float4* xr = (const float4*)(x + (size_t)row * DM);
    float4 v = xr[threadIdx.x];
    float ss = v.x*v.x + v.y*v.y + v.z*v.z + v.w*v.w;
    #pragma unroll
    for (int m = 16; m; m >>= 1) ss += __shfl_xor_sync(~0u, ss, m);
    __shared__ float sred[8];
    __shared__ float stot;
    int wid = threadIdx.x >> 5;
    if ((threadIdx.x & 31) == 0) sred[wid] = ss;
    __syncthreads();
    if (threadIdx.x == 0) {
        float s = 0.f;
        #pragma unroll
        for (int i = 0; i < 8; i++) s += sred[i];
        stot = rsqrtf(s * (1.f / DM) + EPSV);
    }
    __syncthreads();
    float sc = stot;
    float4 wv = ((const float4*)w)[threadIdx.x];
    float o[4] = {v.x*sc*wv.x, v.y*sc*wv.y, v.z*sc*wv.z, v.w*sc*wv.w};
    size_t base = (size_t)row * DM + threadIdx.x * 4;
    #pragma unroll
    for (int j = 0; j < 4; j++) {
        __nv_bfloat16 hi, lo; split_bf16(o[j], hi, lo);
        ohi[base + j] = hi; olo[base + j] = lo;
    }
}

// ================= transpose + bf16 hi/lo split =================
__global__ void transcvt_k(const float* __restrict__ in, int R, int C,
                           __nv_bfloat16* __restrict__ ohi,
                           __nv_bfloat16* __restrict__ olo) {
    __shared__ float t[32][33];
    int ct = blockIdx.x * 32, rt = blockIdx.y * 32;
    int tx = threadIdx.x & 31, ty4 = (threadIdx.x >> 5) * 4;
    #pragma unroll
    for (int j = 0; j < 4; j++) {
        int r = rt + ty4 + j;
        t[ty4 + j][tx] = in[(size_t)r * C + ct + tx];
    }
    __syncthreads();
    #pragma unroll
    for (int j = 0; j < 4; j++) {
        int c = ct + ty4 + j;
        float v = t[tx][ty4 + j];
        __nv_bfloat16 hi, lo; split_bf16(v, hi, lo);
        size_t o = (size_t)c * R + rt + tx;
        ohi[o] = hi; olo[o] = lo;
    }
}

// ================= HMMA bf16x3 GEMM, 4-stage cp.async pipeline ============
// C[M,N] = A[M,K] @ Bt^T, Bt[N,K]. 128x128 CTA tile, BK=32, 8 warps (4x2),
// warp tile 32x64. (Ahi*Bhi + Ahi*Blo + Alo*Bhi).
// EPI 0: plain  1: softplus(v+bias[col])  2: v+resid[row,col]
// EPI 3: fp32 + bf16 hi/lo split stores   4: split-K partial (z slices)
#define SMS    80                    // smem row stride bytes (40 halves)
#define T_A_LO 10240
#define T_B_HI 20480
#define T_B_LO 30720
#define T_STG  40960
#define NSTG   4
#define SMEMB  (NSTG * T_STG)

template<int EPI>
__global__ void __launch_bounds__(256, 1)
mma_gemm_k(const __nv_bfloat16* __restrict__ Ahi, const __nv_bfloat16* __restrict__ Alo, int lda,
           const __nv_bfloat16* __restrict__ Bhi, const __nv_bfloat16* __restrict__ Blo,
           float* __restrict__ C, int ldc, int Kdim, int Ndim,
           const float* __restrict__ bias, const float* __restrict__ resid,
           __nv_bfloat16* __restrict__ Chi, __nv_bfloat16* __restrict__ Clo) {
    extern __shared__ char smem[];
    const uint32_t sdata = smem_to_u32(smem);
    const int tid = threadIdx.x;
    const int wid = tid >> 5, lane = tid & 31;
    const int wm = wid & 3, wn = wid >> 2;          // 4 x 2 warp grid
    const int brow = blockIdx.y * 128;
    const int bcol = blockIdx.x * 128;
    // split-K slice (gridDim.z == 1 for all but EPI 4)
    const int kslice = Kdim / gridDim.z;
    const int kbase  = blockIdx.z * kslice;
    const int NC = kslice >> 5;                     // 32-wide K chunks

    const int lrow = tid >> 2;
    const int lseg = tid & 3;

    float acc[2][8][4];
    #pragma unroll
    for (int a = 0; a < 2; a++)
        #pragma unroll
        for (int b = 0; b < 8; b++)
            #pragma unroll
            for (int c = 0; c < 4; c++) acc[a][b][c] = 0.f;

    auto issue = [&](int s) {
        uint32_t stb = sdata + (s & (NSTG - 1)) * T_STG;
        int koff = kbase + s * 32;
        #pragma unroll
        for (int it = 0; it < 2; it++) {
            int row = it * 64 + lrow;
            uint32_t so = stb + row * SMS + lseg * 16;
            size_t gao = (size_t)(brow + row) * lda + koff + lseg * 8;
            CP_ASYNC16(so,          Ahi + gao);
            CP_ASYNC16(so + T_A_LO, Alo + gao);
            int bn = bcol + row;
            uint32_t p = (bn < Ndim) ? 1u : 0u;
            size_t gbo = (size_t)bn * Kdim + koff + lseg * 8;
            CP_ASYNC16_P(so + T_B_HI, Bhi + gbo, p);
            CP_ASYNC16_P(so + T_B_LO, Blo + gbo, p);
        }
        CP_COMMIT();
    };

    // prefetch 3 stages
    #pragma unroll
    for (int s = 0; s < NSTG - 1; s++) {
        if (s < NC) issue(s); else CP_COMMIT();
    }

    for (int i = 0; i < NC; i++) {
        CP_WAIT(NSTG - 2);          // stage i complete (<=2 newest pending)
        __syncthreads();            // stage i visible; prev reads of stage (i+3)&3 done
        if (i + NSTG - 1 < NC) issue(i + NSTG - 1); else CP_COMMIT();

        uint32_t stb = sdata + (i & (NSTG - 1)) * T_STG;
        const int fr = lane & 15;
        const int fc = (lane >> 4) * 8;
        #pragma unroll
        for (int ks = 0; ks < 32; ks += 16) {
            uint32_t ah[2][4], al[2][4], bh[8][2], bl[8][2];
            #pragma unroll
            for (int mt = 0; mt < 2; mt++) {
                uint32_t ad = stb + (wm * 32 + mt * 16 + fr) * SMS + (ks + fc) * 2;
                LDMX4(ah[mt][0], ah[mt][1], ah[mt][2], ah[mt][3], ad);
                LDMX4(al[mt][0], al[mt][1], al[mt][2], al[mt][3], ad + T_A_LO);
            }
            #pragma unroll
            for (int bt = 0; bt < 4; bt++) {
                uint32_t bd = stb + T_B_HI + (wn * 64 + bt * 16 + fr) * SMS + (ks + fc) * 2;
                uint32_t r0, r1, r2, r3;
                LDMX4(r0, r1, r2, r3, bd);
                bh[bt*2][0] = r0; bh[bt*2][1] = r2;
                bh[bt*2+1][0] = r1; bh[bt*2+1][1] = r3;
                LDMX4(r0, r1, r2, r3, bd + (T_B_LO - T_B_HI));
                bl[bt*2][0] = r0; bl[bt*2][1] = r2;
                bl[bt*2+1][0] = r1; bl[bt*2+1][1] = r3;
            }
            #pragma unroll
            for (int mt = 0; mt < 2; mt++)
                #pragma unroll
                for (int nt = 0; nt < 8; nt++) {
                    MMA16816(acc[mt][nt], ah[mt], bh[nt]);
                    MMA16816(acc[mt][nt], ah[mt], bl[nt]);
                    MMA16816(acc[mt][nt], al[mt], bh[nt]);
                }
        }
    }

    // ---- epilogue ----
    float* Cout = C;
    if (EPI == 4) Cout = C + (size_t)blockIdx.z * MR * XD;
    const int lr = lane >> 2;
    const int lc = (lane & 3) * 2;
    #pragma unroll
    for (int mt = 0; mt < 2; mt++) {
        int r0 = brow + wm * 32 + mt * 16 + lr;
        #pragma unroll
        for (int nt = 0; nt < 8; nt++) {
            int c = bcol + wn * 64 + nt * 8 + lc;
            if (c >= Ndim) continue;
            #pragma unroll
            for (int hh = 0; hh < 2; hh++) {
                int r = r0 + hh * 8;
                float v0 = acc[mt][nt][hh*2], v1 = acc[mt][nt][hh*2+1];
                if (EPI == 1) {
                    v0 = softplus_f(v0 + bias[c]);
                    v1 = softplus_f(v1 + bias[c+1]);
                } else if (EPI == 2) {
                    const float* rr = resid + (size_t)r * ldc + c;
                    v0 += rr[0]; v1 += rr[1];
                }
                float* cp = Cout + (size_t)r * ldc + c;
                *(float2*)cp = make_float2(v0, v1);
                if (EPI == 3) {
                    size_t hb = (size_t)r * ldc + c;
                    __nv_bfloat16 h0, l0, h1, l1;
                    split_bf16(v0, h0, l0); split_bf16(v1, h1, l1);
                    Chi[hb] = h0; Chi[hb+1] = h1;
                    Clo[hb] = l0; Clo[hb+1] = l1;
                }
            }
        }
    }
}

// ================= split-K reduce for x_proj -> xd fp32 + bf16 hi/lo ======
__global__ void xd_reduce_k(const float* __restrict__ part,
                            float* __restrict__ xd,
                            __nv_bfloat16* __restrict__ xhi,
                            __nv_bfloat16* __restrict__ xlo) {
    size_t i = (size_t)blockIdx.x * 256 + threadIdx.x;
    float s = 0.f;
    #pragma unroll
    for (int z = 0; z < XKS; z++) s += part[(size_t)z * MR * XD + i];
    xd[i] = s;
    __nv_bfloat16 hi, lo; split_bf16(s, hi, lo);
    xhi[i] = hi; xlo[i] = lo;
}

// ================= causal depthwise conv (K=4) + SiLU, L-tiled =============
#define CLT 16
__global__ void conv_silu_k(const float* __restrict__ xz,
                            const float* __restrict__ cw,
                            const float* __restrict__ cb,
                            __nv_bfloat16* __restrict__ uhi,
                            __nv_bfloat16* __restrict__ ulo) {
    int d = blockIdx.x * 256 + threadIdx.x;
    int l0 = blockIdx.y * CLT;
    int b = blockIdx.z;
    float4 w = ((const float4*)cw)[d];
    float bias = cb[d];
    const size_t stride = (size_t)2 * DI;
    size_t base = ((size_t)(b * LL) + l0) * stride + d;
    // window: i3 = in[l-3], i2 = in[l-2], i1 = in[l-1]
    float i3 = (l0 >= 3) ? xz[base - 3 * stride] : 0.f;
    float i2 = (l0 >= 2) ? xz[base - 2 * stride] : 0.f;
    float i1 = (l0 >= 1) ? xz[base - 1 * stride] : 0.f;
    size_t ob = ((size_t)(b * LL) + l0) * DI + d;
    #pragma unroll
    for (int j = 0; j < CLT; j++) {
        float cur = xz[base + (size_t)j * stride];
        float acc = bias;
        acc = fmaf(i3, w.x, acc);
        acc = fmaf(i2, w.y, acc);
        acc = fmaf(i1, w.z, acc);
        acc = fmaf(cur, w.w, acc);
        float u = silu_f(acc);
        __nv_bfloat16 hi, lo; split_bf16(u, hi, lo);
        uhi[ob + (size_t)j * DI] = hi;
        ulo[ob + (size_t)j * DI] = lo;
        i3 = i2; i2 = i1; i1 = cur;
    }
}

// ================= selective scan =================
__global__ void __launch_bounds__(256) scan_k(
    const float* __restrict__ xdbl, const float* __restrict__ dt,
    const __nv_bfloat16* __restrict__ uhi, const __nv_bfloat16* __restrict__ ulo,
    const float* __restrict__ Alog, const float* __restrict__ Dp,
    float* __restrict__ y) {
    __shared__ float sBC[64][32];
    int tid = threadIdx.x;
    int g = tid >> 4, n = tid & 15;
    int b = blockIdx.x >> 7;
    int d = ((blockIdx.x & 127) << 4) + g;
    float An = -expf(Alog[d * NS + n]);
    float Dd = Dp[d];
    float h = 0.f;
    size_t rowbase = (size_t)b * LL;
    for (int c = 0; c < LL / 64; c++) {
        __syncthreads();
        for (int i = tid; i < 64 * 32; i += 256) {
            int tt = i >> 5, col = i & 31;
            sBC[tt][col] = xdbl[(rowbase + c * 64 + tt) * XD + 64 + col];
        }
        __syncthreads();
        for (int tt = 0; tt < 64; tt++) {
            size_t idx = (rowbase + c * 64 + tt) * DI + d;
            float dtv = __ldg(dt + idx);
            float uv  = __bfloat162float(uhi[idx]) + __bfloat162float(ulo[idx]);
            float Bv = sBC[tt][n];
            float Cv = sBC[tt][16 + n];
            float dA = __expf(dtv * An);
            h = fmaf(dA, h, dtv * Bv * uv);
            float p = h * Cv;
            p += __shfl_xor_sync(0xffffffffu, p, 8, 16);
            p += __shfl_xor_sync(0xffffffffu, p, 4, 16);
            p += __shfl_xor_sync(0xffffffffu, p, 2, 16);
            p += __shfl_xor_sync(0xffffffffu, p, 1, 16);
            if (n == 0) y[idx] = p + uv * Dd;
        }
    }
}

// ================= gate: yg = y * silu(z) -> bf16 hi/lo =================
__global__ void gate_k(const float* __restrict__ xz, const float* __restrict__ y,
                       __nv_bfloat16* __restrict__ ghi, __nv_bfloat16* __restrict__ glo) {
    size_t i = (size_t)blockIdx.x * blockDim.x + threadIdx.x;
    size_t m = i >> 9;
    size_t c = i & 511;
    float4 z  = ((const float4*)xz)[m * 1024 + 512 + c];
    float4 yv = ((const float4*)y)[i];
    float o[4] = {yv.x * silu_f(z.x), yv.y * silu_f(z.y),
                  yv.z * silu_f(z.z), yv.w * silu_f(z.w)};
    size_t base = i * 4;
    #pragma unroll
    for (int j = 0; j < 4; j++) {
        __nv_bfloat16 hi, lo; split_bf16(o[j], hi, lo);
        ghi[base + j] = hi; glo[base + j] = lo;
    }
}

// ================= launcher =================
extern "C" void kernel_launch(void* const* d_in, const int* in_sizes, int n_in,
                              void* d_out, int out_size) {
    const float* x         = (const float*)d_in[0];
    const float* norm_w    = (const float*)d_in[2];
    const float* in_proj_w = (const float*)d_in[3];
    const float* conv_w    = (const float*)d_in[4];
    const float* conv_b    = (const float*)d_in[5];
    const float* x_proj_w  = (const float*)d_in[6];
    const float* dt_proj_w = (const float*)d_in[7];
    const float* dt_proj_b = (const float*)d_in[8];
    const float* A_log     = (const float*)d_in[9];
    const float* Dp        = (const float*)d_in[10];
    const float* out_proj_w= (const float*)d_in[11];
    float* out = (float*)d_out;

    float *xz, *xd, *xdp, *dt, *y;
    cudaGetSymbolAddress((void**)&xz,  g_xz);
    cudaGetSymbolAddress((void**)&xd,  g_xd);
    cudaGetSymbolAddress((void**)&xdp, g_xdp);
    cudaGetSymbolAddress((void**)&dt,  g_dt);
    cudaGetSymbolAddress((void**)&y,   g_y);
    __nv_bfloat16 *h_hi, *h_lo, *u_hi, *u_lo, *xd_hi, *xd_lo, *yg_hi, *yg_lo;
    __nv_bfloat16 *wi_hi, *wi_lo, *wx_hi, *wx_lo, *wd_hi, *wd_lo, *wo_hi, *wo_lo;
    cudaGetSymbolAddress((void**)&h_hi,  g_h_hi);  cudaGetSymbolAddress((void**)&h_lo,  g_h_lo);
    cudaGetSymbolAddress((void**)&u_hi,  g_u_hi);  cudaGetSymbolAddress((void**)&u_lo,  g_u_lo);
    cudaGetSymbolAddress((void**)&xd_hi, g_xd_hi); cudaGetSymbolAddress((void**)&xd_lo, g_xd_lo);
    cudaGetSymbolAddress((void**)&yg_hi, g_yg_hi); cudaGetSymbolAddress((void**)&yg_lo, g_yg_lo);
    cudaGetSymbolAddress((void**)&wi_hi, g_wi_hi); cudaGetSymbolAddress((void**)&wi_lo, g_wi_lo);
    cudaGetSymbolAddress((void**)&wx_hi, g_wx_hi); cudaGetSymbolAddress((void**)&wx_lo, g_wx_lo);
    cudaGetSymbolAddress((void**)&wd_hi, g_wd_hi); cudaGetSymbolAddress((void**)&wd_lo, g_wd_lo);
    cudaGetSymbolAddress((void**)&wo_hi, g_wo_hi); cudaGetSymbolAddress((void**)&wo_lo, g_wo_lo);

    cudaFuncSetAttribute(mma_gemm_k<0>, cudaFuncAttributeMaxDynamicSharedMemorySize, SMEMB);
    cudaFuncSetAttribute(mma_gemm_k<1>, cudaFuncAttributeMaxDynamicSharedMemorySize, SMEMB);
    cudaFuncSetAttribute(mma_gemm_k<2>, cudaFuncAttributeMaxDynamicSharedMemorySize, SMEMB);
    cudaFuncSetAttribute(mma_gemm_k<4>, cudaFuncAttributeMaxDynamicSharedMemorySize, SMEMB);

    // 0. weight transpose + bf16 split
    transcvt_k<<<dim3((2*DI)/32, DM/32), 256>>>(in_proj_w, DM, 2*DI, wi_hi, wi_lo);
    transcvt_k<<<dim3(XD/32, DI/32), 256>>>(x_proj_w, DI, XD, wx_hi, wx_lo);
    transcvt_k<<<dim3(DI/32, RR/32), 256>>>(dt_proj_w, RR, DI, wd_hi, wd_lo);
    transcvt_k<<<dim3(DM/32, DI/32), 256>>>(out_proj_w, DI, DM, wo_hi, wo_lo);
    // 1. h = rmsnorm(x) -> bf16 hi/lo
    rmsnorm_k<<<MR, 256>>>(x, norm_w, h_hi, h_lo);
    // 2. xz = h @ in_proj_w  (4096x1024 @ 1024x4096)
    mma_gemm_k<0><<<dim3((2*DI)/128, MR/128), 256, SMEMB>>>(
        h_hi, h_lo, DM, wi_hi, wi_lo, xz, 2*DI, DM, 2*DI,
        nullptr, nullptr, nullptr, nullptr);
    // 3. u = silu(causal_conv(xz[..., :DI])) -> bf16 hi/lo
    conv_silu_k<<<dim3(DI/256, LL/CLT, BB), 256>>>(xz, conv_w, conv_b, u_hi, u_lo);
    // 4. xdbl = u @ x_proj_w  (4096x2048 @ 2048x96), split-K x8 + reduce
    mma_gemm_k<4><<<dim3(1, MR/128, XKS), 256, SMEMB>>>(
        u_hi, u_lo, DI, wx_hi, wx_lo, xdp, XD, DI, XD,
        nullptr, nullptr, nullptr, nullptr);
    xd_reduce_k<<<(MR * XD) / 256, 256>>>(xdp, xd, xd_hi, xd_lo);
    // 5. dt = softplus(xdbl[:, :64] @ dt_proj_w + b)  (4096x64 @ 64x2048)
    mma_gemm_k<1><<<dim3(DI/128, MR/128), 256, SMEMB>>>(
        xd_hi, xd_lo, XD, wd_hi, wd_lo, dt, DI, RR, DI,
        dt_proj_b, nullptr, nullptr, nullptr);
    // 6. selective scan -> y fp32 (includes + u*D)
    scan_k<<<BB * DI / 16, 256>>>(xd, dt, u_hi, u_lo, A_log, Dp, y);
    // 7. yg = y * silu(z) -> bf16 hi/lo
    gate_k<<<(MR * DI / 4) / 256, 256>>>(xz, y, yg_hi, yg_lo);
    // 8. out = x + yg @ out_proj_w  (4096x2048 @ 2048x1024)
    mma_gemm_k<2><<<dim3(DM/128, MR/128), 256, SMEMB>>>(
        yg_hi, yg_lo, DI, wo_hi, wo_lo, out, DM, DI, DM,
        nullptr, x, nullptr, nullptr);
}